// round 1
// baseline (speedup 1.0000x reference)
#include <cuda_runtime.h>
#include <cstdint>

// out[b,c, patch p, a, d] = x[b,c, patch (p+c)&63, a, d] + pos[c*64 + (p+c)&63]
// B=8, C=64, H=W=512, patches 8x8 of 64x64, PN=64.
//
// Pure HBM-streaming permutation+bias. float4 per thread, fully coalesced.

#define B_  8
#define C_  64
#define H_  512
#define W_  512
#define W4  (W_/4)          // 128 float4 per row
#define N4  ((long long)B_ * C_ * H_ * W4)   // 33,554,432

__global__ __launch_bounds__(256) void crosspatch_kernel(
    const float4* __restrict__ x4,
    const float*  __restrict__ pos,   // [64,64]
    float4* __restrict__ out4)
{
    unsigned idx = blockIdx.x * 256u + threadIdx.x;   // < 2^25, fits easily

    // decompose: idx = ((b*64 + c)*512 + h)*128 + w4
    unsigned w4 = idx & 127u;
    unsigned t  = idx >> 7;
    unsigned h  = t & 511u;
    unsigned bc = t >> 9;            // b*64 + c
    unsigned c  = bc & 63u;

    unsigned pw = w4 >> 4;           // patch col (0..7), 16 float4 per patch row
    unsigned ph = h >> 6;            // patch row (0..7)
    unsigned a  = h & 63u;           // row inside patch
    unsigned p  = (ph << 3) | pw;    // dest patch id
    unsigned sp = (p + c) & 63u;     // source patch id
    unsigned sph = sp >> 3;
    unsigned spw = sp & 7u;

    // source float4 offset: ((bc)*512 + sph*64 + a)*128 + spw*16 + (w4 & 15)
    unsigned src = ((bc << 9) + (sph << 6) + a) * 128u + (spw << 4) + (w4 & 15u);

    float bias = __ldg(&pos[(c << 6) + sp]);
    float4 v = __ldg(&x4[src]);
    v.x += bias; v.y += bias; v.z += bias; v.w += bias;
    out4[idx] = v;
}

extern "C" void kernel_launch(void* const* d_in, const int* in_sizes, int n_in,
                              void* d_out, int out_size)
{
    const float4* x4  = (const float4*)d_in[0];
    const float*  pos = (const float*)d_in[1];   // 4096 elems (1,1,64,64,1,1)
    float4* out4 = (float4*)d_out;

    unsigned blocks = (unsigned)(N4 / 256);      // 131072
    crosspatch_kernel<<<blocks, 256>>>(x4, pos, out4);
}

// round 2
// speedup vs baseline: 1.0264x; 1.0264x over previous
#include <cuda_runtime.h>
#include <cstdint>

// out[b,c, patch p, a, d] = x[b,c, patch (p+c)&63, a, d] + pos[c*64 + (p+c)&63]
// B=8, C=64, H=W=512, patches 8x8 of 64x64, PN=64.
//
// Pure HBM-streaming permutation+bias.
// Each thread: 4 float4 chunks at row-stride 16 within its patch column
// (src and dst strides identical = 16*128 float4). Front-batched LDG.128 x4
// for MLP, streaming (.cs) loads/stores since data is touched exactly once.

#define B_  8
#define C_  64
#define W4  128                    // float4 per image row
#define ROWSTEP (16 * W4)          // 2048 float4: 16 rows
#define NTHREADS_TOTAL (8u * 64u * 8u * 16u * 128u)   // 8,388,608

__global__ __launch_bounds__(256) void crosspatch_kernel(
    const float4* __restrict__ x4,
    const float*  __restrict__ pos,   // [64,64]
    float4* __restrict__ out4)
{
    unsigned idx = blockIdx.x * 256u + threadIdx.x;

    // idx = (((bc)*8 + ph)*16 + a0)*128 + w4   ; thread covers a = a0 + {0,16,32,48}
    unsigned w4 = idx & 127u;
    unsigned t  = idx >> 7;
    unsigned a0 = t & 15u;
    unsigned t2 = t >> 4;
    unsigned ph = t2 & 7u;
    unsigned bc = t2 >> 3;           // b*64 + c
    unsigned c  = bc & 63u;

    unsigned pw = w4 >> 4;           // dest patch col
    unsigned p  = (ph << 3) | pw;    // dest patch id
    unsigned sp = (p + c) & 63u;     // source patch id
    unsigned sph = sp >> 3;
    unsigned spw = sp & 7u;

    unsigned dst = ((bc << 9) + (ph  << 6) + a0) * 128u + w4;
    unsigned src = ((bc << 9) + (sph << 6) + a0) * 128u + (spw << 4) + (w4 & 15u);

    float bias = __ldg(&pos[(c << 6) + sp]);

    // front-batch 4 independent streaming loads
    float4 v0 = __ldcs(&x4[src              ]);
    float4 v1 = __ldcs(&x4[src +     ROWSTEP]);
    float4 v2 = __ldcs(&x4[src + 2 * ROWSTEP]);
    float4 v3 = __ldcs(&x4[src + 3 * ROWSTEP]);

    v0.x += bias; v0.y += bias; v0.z += bias; v0.w += bias;
    v1.x += bias; v1.y += bias; v1.z += bias; v1.w += bias;
    v2.x += bias; v2.y += bias; v2.z += bias; v2.w += bias;
    v3.x += bias; v3.y += bias; v3.z += bias; v3.w += bias;

    __stcs(&out4[dst              ], v0);
    __stcs(&out4[dst +     ROWSTEP], v1);
    __stcs(&out4[dst + 2 * ROWSTEP], v2);
    __stcs(&out4[dst + 3 * ROWSTEP], v3);
}

extern "C" void kernel_launch(void* const* d_in, const int* in_sizes, int n_in,
                              void* d_out, int out_size)
{
    const float4* x4  = (const float4*)d_in[0];
    const float*  pos = (const float*)d_in[1];
    float4* out4 = (float4*)d_out;

    unsigned blocks = NTHREADS_TOTAL / 256u;   // 32768
    crosspatch_kernel<<<blocks, 256>>>(x4, pos, out4);
}